// round 1
// baseline (speedup 1.0000x reference)
#include <cuda_runtime.h>
#include <math.h>

#define B_   8
#define T_   1024
#define E_   1024
#define NB_  10
#define H_   16
#define HD_  64
#define ROWS (B_*T_)   // 8192

// ---------------- scratch (static device memory; no allocs) ----------------
__device__ float g_h1[ROWS*E_];          // 32 MB
__device__ float g_h2[ROWS*(E_/2)];      // 16 MB (reused for scorer hidden)
__device__ float g_scores[ROWS*NB_];
__device__ float g_xrot[ROWS*E_];        // 32 MB
__device__ float g_qkv[ROWS*3*E_];       // 96 MB
__device__ float g_P[134217728];         // 512 MB : B*H*T*T
__device__ float g_ctx[ROWS*E_];         // 32 MB
__device__ float g_attnout[ROWS*E_];     // 32 MB
__device__ float g_div[ROWS*E_];         // 32 MB
__device__ float g_base[ROWS];
__device__ float g_qm[ROWS*4];
__device__ float g_opp[ROWS];
__device__ float g_amsum[B_*T_];
__device__ float g_wa[B_];
__device__ float g_anom[ROWS];
__device__ float g_aq[ROWS*4];
__device__ float g_pres[ROWS];
__device__ float g_inten[ROWS];

// ---------------- helpers ----------------
__device__ __forceinline__ float geluf(float v){
    return 0.5f*v*(1.0f + erff(v*0.70710678118654752440f));
}
__device__ __forceinline__ float sigm(float v){ return 1.0f/(1.0f+expf(-v)); }

__device__ __forceinline__ float bred_sum(float v){
    __shared__ float sh[32];
    int lane = threadIdx.x & 31, w = threadIdx.x >> 5, nw = blockDim.x >> 5;
    #pragma unroll
    for (int o=16;o>0;o>>=1) v += __shfl_down_sync(0xffffffffu, v, o);
    if (lane==0) sh[w]=v;
    __syncthreads();
    if (w==0){
        v = (lane<nw)?sh[lane]:0.f;
        #pragma unroll
        for (int o=16;o>0;o>>=1) v += __shfl_down_sync(0xffffffffu, v, o);
        if (lane==0) sh[0]=v;
    }
    __syncthreads();
    float r = sh[0];
    __syncthreads();
    return r;
}

__device__ __forceinline__ float bred_max(float v){
    __shared__ float shm[32];
    int lane = threadIdx.x & 31, w = threadIdx.x >> 5, nw = blockDim.x >> 5;
    #pragma unroll
    for (int o=16;o>0;o>>=1) v = fmaxf(v, __shfl_down_sync(0xffffffffu, v, o));
    if (lane==0) shm[w]=v;
    __syncthreads();
    if (w==0){
        v = (lane<nw)?shm[lane]:-3.4e38f;
        #pragma unroll
        for (int o=16;o>0;o>>=1) v = fmaxf(v, __shfl_down_sync(0xffffffffu, v, o));
        if (lane==0) shm[0]=v;
    }
    __syncthreads();
    float r = shm[0];
    __syncthreads();
    return r;
}

__device__ __forceinline__ void qmulp(const float* q, const float* r, float* o){
    o[0]=q[0]*r[0]-q[1]*r[1]-q[2]*r[2]-q[3]*r[3];
    o[1]=q[0]*r[1]+q[1]*r[0]+q[2]*r[3]-q[3]*r[2];
    o[2]=q[0]*r[2]-q[1]*r[3]+q[2]*r[0]+q[3]*r[1];
    o[3]=q[0]*r[3]+q[1]*r[2]-q[2]*r[1]+q[3]*r[0];
}

// ---------------- generic strided/batched SGEMM ----------------
// C = alpha * A @ op(B) + bias  with optional activation.
// TRB=1: op(B)=B^T (B is [N,K] row-major).  TRB=0: op(B)=B (B is [K,N]).
// ACT: 0 none, 1 GELU(exact), 2 ReLU
// Batch: z in grid.z ; zb=z/Hdiv, zh=z%Hdiv ; ptr += zb*s?b + zh*s?h
template<int TRB, int ACT>
__global__ void __launch_bounds__(256) sgemm_k(
    const float* __restrict__ Ag, const float* __restrict__ Bg,
    const float* __restrict__ bias, float* __restrict__ Cg,
    int M, int N, int K, int lda, int ldb, int ldc,
    long sAb, long sAh, long sBb, long sBh, long sCb, long sCh,
    int Hdiv, float alpha)
{
    int z  = blockIdx.z;
    int zb = z / Hdiv, zh = z - zb*Hdiv;
    const float* A = Ag + zb*sAb + zh*sAh;
    const float* B = Bg + zb*sBb + zh*sBh;
    float*       C = Cg + zb*sCb + zh*sCh;

    __shared__ float As[8][136];
    __shared__ float Bs[8][136];

    int tid = threadIdx.x;
    int tx = tid & 15, ty = tid >> 4;
    int row0 = blockIdx.y*128, col0 = blockIdx.x*128;

    float acc[8][8];
    #pragma unroll
    for (int i=0;i<8;i++)
        #pragma unroll
        for (int j=0;j<8;j++) acc[i][j]=0.f;

    for (int k0=0;k0<K;k0+=8){
        #pragma unroll
        for (int i=0;i<4;i++){
            int lid = tid + i*256;
            int r = lid >> 3, c = lid & 7;
            int gr = row0 + r, gc = k0 + c;
            As[c][r] = (gr<M && gc<K) ? A[(long)gr*lda + gc] : 0.f;
        }
        #pragma unroll
        for (int i=0;i<4;i++){
            int lid = tid + i*256;
            if (TRB){
                int r = lid >> 3, c = lid & 7;
                int gn = col0 + r, gc = k0 + c;
                Bs[c][r] = (gn<N && gc<K) ? B[(long)gn*ldb + gc] : 0.f;
            } else {
                int kk = lid >> 7, n = lid & 127;
                int gk = k0 + kk, gn = col0 + n;
                Bs[kk][n] = (gk<K && gn<N) ? B[(long)gk*ldb + gn] : 0.f;
            }
        }
        __syncthreads();
        #pragma unroll
        for (int kk=0;kk<8;kk++){
            float a[8], b[8];
            #pragma unroll
            for (int i=0;i<8;i++) a[i] = As[kk][ty + 16*i];
            #pragma unroll
            for (int j=0;j<8;j++) b[j] = Bs[kk][tx + 16*j];
            #pragma unroll
            for (int i=0;i<8;i++)
                #pragma unroll
                for (int j=0;j<8;j++) acc[i][j] = fmaf(a[i], b[j], acc[i][j]);
        }
        __syncthreads();
    }

    #pragma unroll
    for (int i=0;i<8;i++){
        int gr = row0 + ty + 16*i;
        if (gr>=M) continue;
        #pragma unroll
        for (int j=0;j<8;j++){
            int gn = col0 + tx + 16*j;
            if (gn>=N) continue;
            float v = acc[i][j]*alpha;
            if (bias) v += __ldg(&bias[gn]);
            if (ACT==1)      v = geluf(v);
            else if (ACT==2) v = fmaxf(v, 0.f);
            C[(long)gr*ldc + gn] = v;
        }
    }
}

// ---------------- LayerNorm (biased var) + exact GELU, per row ----------------
__global__ void ln_gelu_k(const float* __restrict__ h, const float* __restrict__ g,
                          const float* __restrict__ bb, float* __restrict__ out)
{
    int row = blockIdx.x;
    const float* hr = h + (long)row*E_;
    float v[4]; float s=0.f, ss=0.f;
    #pragma unroll
    for (int i=0;i<4;i++){ v[i]=hr[threadIdx.x + i*256]; s+=v[i]; ss+=v[i]*v[i]; }
    s  = bred_sum(s);
    ss = bred_sum(ss);
    float mu   = s*(1.f/E_);
    float var  = ss*(1.f/E_) - mu*mu;
    float rstd = rsqrtf(var + 1e-5f);
    float* orow = out + (long)row*E_;
    #pragma unroll
    for (int i=0;i<4;i++){
        int c = threadIdx.x + i*256;
        float y = (v[i]-mu)*rstd*g[c] + bb[c];
        orow[c] = geluf(y);
    }
}

// ---------------- bias_scores = sigmoid(h2 @ w3^T + b3), N=10, K=512 --------
__global__ void bias_scores_k(const float* __restrict__ h2, const float* __restrict__ w3,
                              const float* __restrict__ b3, float* __restrict__ out)
{
    __shared__ float sw[NB_*512];
    for (int i=threadIdx.x;i<NB_*512;i+=256) sw[i]=w3[i];
    __syncthreads();
    int warp = threadIdx.x>>5, lane = threadIdx.x&31;
    long row = (long)blockIdx.x*8 + warp;
    const float* hr = h2 + row*512;
    float acc[NB_];
    #pragma unroll
    for (int j=0;j<NB_;j++) acc[j]=0.f;
    for (int k=lane;k<512;k+=32){
        float hv = hr[k];
        #pragma unroll
        for (int j=0;j<NB_;j++) acc[j] = fmaf(hv, sw[j*512+k], acc[j]);
    }
    #pragma unroll
    for (int j=0;j<NB_;j++){
        #pragma unroll
        for (int o=16;o>0;o>>=1) acc[j]+=__shfl_down_sync(0xffffffffu,acc[j],o);
    }
    if (lane==0){
        #pragma unroll
        for (int j=0;j<NB_;j++) out[row*NB_+j] = sigm(acc[j]+b3[j]);
    }
}

// ---------------- sequential quaternion bias correction ----------------
__global__ void bias_rotate_k(const float* __restrict__ x, const float* __restrict__ scores,
                              const float* __restrict__ quats, const float* __restrict__ thr,
                              float* __restrict__ out)
{
    int row = blockIdx.x;
    __shared__ float sq[NB_*4];
    __shared__ float ssc[NB_];
    if (threadIdx.x<NB_*4) sq[threadIdx.x]=quats[threadIdx.x];
    if (threadIdx.x<NB_)   ssc[threadIdx.x]=scores[(long)row*NB_+threadIdx.x];
    __syncthreads();
    float th = *thr;
    float4 vv = ((const float4*)x)[(long)row*256 + threadIdx.x];
    float r[4]={vv.x,vv.y,vv.z,vv.w};
    #pragma unroll
    for (int k=0;k<NB_;k++){
        if (ssc[k]>th){
            float o[4];
            qmulp(&sq[k*4], r, o);
            r[0]=o[0];r[1]=o[1];r[2]=o[2];r[3]=o[3];
        }
    }
    ((float4*)out)[(long)row*256+threadIdx.x] = make_float4(r[0],r[1],r[2],r[3]);
}

// ---------------- misc small kernels ----------------
__global__ void zero_k(float* p, int n){
    int i = blockIdx.x*blockDim.x + threadIdx.x;
    if (i<n) p[i]=0.f;
}

__global__ void absdiff_k(const float* __restrict__ a, const float* __restrict__ b,
                          float* __restrict__ o, int n){
    int i = blockIdx.x*blockDim.x + threadIdx.x;
    if (i<n) o[i]=fabsf(a[i]-b[i]);
}

// ---------------- softmax rows of P in-place + accumulate column sums -------
// grid: (T/16, H, B), block 256. Each thread owns 4 fixed columns.
__global__ void softmax_colsum_k(float* __restrict__ P, float* __restrict__ amsum)
{
    int b=blockIdx.z, h=blockIdx.y, q0=blockIdx.x*16;
    float* base = P + ((size_t)(b*H_+h)*T_ + q0)*(size_t)T_;
    float lacc[4]={0.f,0.f,0.f,0.f};
    for (int r=0;r<16;r++){
        float* rowp = base + (size_t)r*T_;
        float v[4]; float m=-3.4e38f;
        #pragma unroll
        for (int i=0;i<4;i++){ v[i]=rowp[threadIdx.x+i*256]; m=fmaxf(m,v[i]); }
        m = bred_max(m);
        float s=0.f;
        #pragma unroll
        for (int i=0;i<4;i++){ v[i]=expf(v[i]-m); s+=v[i]; }
        s = bred_sum(s);
        float inv = 1.f/s;
        #pragma unroll
        for (int i=0;i<4;i++){
            float p = v[i]*inv;
            rowp[threadIdx.x+i*256]=p;
            lacc[i]+=p;
        }
    }
    #pragma unroll
    for (int i=0;i<4;i++) atomicAdd(&amsum[b*T_ + threadIdx.x + i*256], lacc[i]);
}

// ---------------- base = sigmoid(ReLU-hidden @ ws2^T + bs2), N=1 ------------
__global__ void base_k(const float* __restrict__ hs, const float* __restrict__ ws2,
                       const float* __restrict__ bs2, float* __restrict__ out){
    int warp=threadIdx.x>>5, lane=threadIdx.x&31;
    long row=(long)blockIdx.x*8+warp;
    const float* hr = hs + row*512;
    float acc=0.f;
    for (int k=lane;k<512;k+=32) acc = fmaf(hr[k], ws2[k], acc);
    #pragma unroll
    for (int o=16;o>0;o>>=1) acc+=__shfl_down_sync(0xffffffffu,acc,o);
    if (lane==0) out[row]=sigm(acc+bs2[0]);
}

// ---------------- normalized-quaternion row means ----------------
__global__ void qmean_k(const float* __restrict__ x, float* __restrict__ qm){
    int row=blockIdx.x;
    float4 vv = ((const float4*)x)[(long)row*256+threadIdx.x];
    float n = sqrtf(vv.x*vv.x+vv.y*vv.y+vv.z*vv.z+vv.w*vv.w);
    float inv = 1.f/(n+1e-8f);
    float s0=bred_sum(vv.x*inv);
    float s1=bred_sum(vv.y*inv);
    float s2=bred_sum(vv.z*inv);
    float s3=bred_sum(vv.w*inv);
    if (threadIdx.x==0){
        qm[row*4+0]=s0*(1.f/256.f); qm[row*4+1]=s1*(1.f/256.f);
        qm[row*4+2]=s2*(1.f/256.f); qm[row*4+3]=s3*(1.f/256.f);
    }
}

__global__ void opp_k(const float* __restrict__ qm, float* __restrict__ opp){
    int idx = blockIdx.x*blockDim.x+threadIdx.x;
    if (idx>=ROWS) return;
    int t = idx & (T_-1);
    if (t==0){ opp[idx]=0.f; return; }
    float d = qm[idx*4+0]*qm[(idx-1)*4+0] + qm[idx*4+1]*qm[(idx-1)*4+1]
            + qm[idx*4+2]*qm[(idx-1)*4+2] + qm[idx*4+3]*qm[(idx-1)*4+3];
    opp[idx] = fminf(fmaxf(-d,0.f),1.f);
}

__global__ void wa_k(const float* __restrict__ amsum, const float* __restrict__ opp,
                     float* __restrict__ wa){
    int b=blockIdx.x;
    float s=0.f;
    const float scale = 1.f/((float)H_*(float)T_);
    for (int t=threadIdx.x;t<T_;t+=256)
        s += amsum[b*T_+t]*scale*opp[b*T_+t];
    s = bred_sum(s);
    if (threadIdx.x==0) wa[b]=s;
}

// ---------------- windowed (w=5) z-score anomalies ----------------
__global__ void anom_k(const float* __restrict__ x, float* __restrict__ out){
    int row=blockIdx.x; int b=row>>10; int t=row&1023;
    int st = t-2 > 0 ? t-2 : 0;
    int en = t+3 < T_ ? t+3 : T_;
    float n=(float)(en-st);
    float z=0.f;
    const float* xb = x + ((size_t)b*T_)*E_;
    for (int e=threadIdx.x;e<E_;e+=256){
        float s=0.f, ss=0.f;
        for (int w=st;w<en;w++){
            float v = xb[(size_t)w*E_+e];
            s+=v; ss+=v*v;
        }
        float mean=s/n;
        float var=(ss - s*s/n)/(n-1.f);
        float sd=sqrtf(fmaxf(var,0.f))+1e-8f;
        float xv=xb[(size_t)t*E_+e];
        z += fabsf(xv-mean)/sd;
    }
    z = bred_sum(z);
    if (threadIdx.x==0) out[row]=z*(1.f/E_);
}

// ---------------- combine scores + phase quaternion params (block per b) ----
__global__ void combine_k(const float* __restrict__ opp, const float* __restrict__ wa,
                          const float* __restrict__ anom, const float* __restrict__ base,
                          const float* __restrict__ phase,
                          float* __restrict__ aq, float* __restrict__ pres,
                          float* __restrict__ inten)
{
    int b=blockIdx.x, t=threadIdx.x;
    long idx=(long)b*T_+t;
    float o_n  = sigm(opp[idx]*2.f);
    float acv  = (t < T_-1) ? wa[b] : 0.f;
    float a_n  = sigm(acv*2.f);
    float an_n = sigm(anom[idx]-1.f);
    float so=bred_sum(o_n),   sso=bred_sum(o_n*o_n);
    float sa=bred_sum(a_n),   ssa=bred_sum(a_n*a_n);
    float sn=bred_sum(an_n),  ssn=bred_sum(an_n*an_n);
    const float N=(float)T_;
    float std_o = sqrtf(fmaxf((sso - so*so/N)/(N-1.f),0.f));
    float std_a = sqrtf(fmaxf((ssa - sa*sa/N)/(N-1.f),0.f));
    float std_n = sqrtf(fmaxf((ssn - sn*sn/N)/(N-1.f),0.f));
    float combined = (o_n*(std_o+0.1f)+a_n*(std_a+0.1f)+an_n*(std_n+0.1f))*(1.f/3.f);
    float cs = sigm((base[idx]+combined-0.5f)*2.f);          // /TEMP, TEMP=0.5
    float it = fminf(fmaxf((cs-0.3f)*(1.f/0.7f),0.f),1.f);
    float stg = 0.5f*it;                                     // PHASE_STRENGTH
    float a0 = phase[0]*stg, a1=phase[1]*stg, a2=phase[2]*stg;
    float chv=cosf(a0*0.5f), shv=sinf(a0*0.5f);
    aq[idx*4+0]=chv;
    aq[idx*4+1]=shv*cosf(a1);
    aq[idx*4+2]=shv*sinf(a1)*cosf(a2);
    aq[idx*4+3]=shv*sinf(a1)*sinf(a2);
    pres[idx]=1.f-stg*0.5f;
    inten[idx]=it;
}

// ---------------- final phase-filter rotation ----------------
__global__ void final_k(const float* __restrict__ x, const float* __restrict__ aq,
                        const float* __restrict__ pres, const float* __restrict__ inten,
                        float* __restrict__ out)
{
    int row=blockIdx.x;
    float4 vv=((const float4*)x)[(long)row*256+threadIdx.x];
    float r[4]={vv.x,vv.y,vv.z,vv.w};
    float it=inten[row];
    float res[4];
    if (it>0.1f){
        float q[4]={aq[row*4+0],aq[row*4+1],aq[row*4+2],aq[row*4+3]};
        float o[4]; qmulp(q,r,o);
        float p=pres[row];
        #pragma unroll
        for (int c=0;c<4;c++) res[c]=p*r[c]+(1.f-p)*o[c];
    } else {
        #pragma unroll
        for (int c=0;c<4;c++) res[c]=r[c];
    }
    ((float4*)out)[(long)row*256+threadIdx.x]=make_float4(res[0],res[1],res[2],res[3]);
}

// ---------------- host launcher ----------------
extern "C" void kernel_launch(void* const* d_in, const int* in_sizes, int n_in,
                              void* d_out, int out_size)
{
    const float* x          = (const float*)d_in[0];
    const float* w1         = (const float*)d_in[1];
    const float* b1         = (const float*)d_in[2];
    const float* ln_g       = (const float*)d_in[3];
    const float* ln_b       = (const float*)d_in[4];
    const float* w2         = (const float*)d_in[5];
    const float* b2         = (const float*)d_in[6];
    const float* w3         = (const float*)d_in[7];
    const float* b3         = (const float*)d_in[8];
    const float* bias_quats = (const float*)d_in[9];
    const float* bias_thr   = (const float*)d_in[10];
    const float* w_in       = (const float*)d_in[11];
    const float* b_in       = (const float*)d_in[12];
    const float* w_out      = (const float*)d_in[13];
    const float* b_out      = (const float*)d_in[14];
    const float* ws1        = (const float*)d_in[15];
    const float* bs1        = (const float*)d_in[16];
    const float* ws2        = (const float*)d_in[17];
    const float* bs2        = (const float*)d_in[18];
    const float* phase      = (const float*)d_in[19];
    float* out = (float*)d_out;

    float *p_h1,*p_h2,*p_scores,*p_xrot,*p_qkv,*p_P,*p_ctx,*p_attnout,*p_div,
          *p_base,*p_qm,*p_opp,*p_amsum,*p_wa,*p_anom,*p_aq,*p_pres,*p_inten;
    cudaGetSymbolAddress((void**)&p_h1,      g_h1);
    cudaGetSymbolAddress((void**)&p_h2,      g_h2);
    cudaGetSymbolAddress((void**)&p_scores,  g_scores);
    cudaGetSymbolAddress((void**)&p_xrot,    g_xrot);
    cudaGetSymbolAddress((void**)&p_qkv,     g_qkv);
    cudaGetSymbolAddress((void**)&p_P,       g_P);
    cudaGetSymbolAddress((void**)&p_ctx,     g_ctx);
    cudaGetSymbolAddress((void**)&p_attnout, g_attnout);
    cudaGetSymbolAddress((void**)&p_div,     g_div);
    cudaGetSymbolAddress((void**)&p_base,    g_base);
    cudaGetSymbolAddress((void**)&p_qm,      g_qm);
    cudaGetSymbolAddress((void**)&p_opp,     g_opp);
    cudaGetSymbolAddress((void**)&p_amsum,   g_amsum);
    cudaGetSymbolAddress((void**)&p_wa,      g_wa);
    cudaGetSymbolAddress((void**)&p_anom,    g_anom);
    cudaGetSymbolAddress((void**)&p_aq,      g_aq);
    cudaGetSymbolAddress((void**)&p_pres,    g_pres);
    cudaGetSymbolAddress((void**)&p_inten,   g_inten);

    const long TT = (long)T_*T_;

    // 1) h1 = x @ w1^T + b1
    sgemm_k<1,0><<<dim3(8,64,1),256>>>(x, w1, b1, p_h1,
        ROWS, E_, E_, E_, E_, E_, 0,0,0,0,0,0, 1, 1.f);
    // 2) LayerNorm + GELU (in place)
    ln_gelu_k<<<ROWS,256>>>(p_h1, ln_g, ln_b, p_h1);
    // 3) h2 = GELU(h1 @ w2^T + b2)
    sgemm_k<1,1><<<dim3(4,64,1),256>>>(p_h1, w2, b2, p_h2,
        ROWS, E_/2, E_, E_, E_, E_/2, 0,0,0,0,0,0, 1, 1.f);
    // 4) bias scores
    bias_scores_k<<<ROWS/8,256>>>(p_h2, w3, b3, p_scores);
    // 5) quaternion bias correction
    bias_rotate_k<<<ROWS,256>>>(x, p_scores, bias_quats, bias_thr, p_xrot);
    // 6) QKV projection
    sgemm_k<1,0><<<dim3(24,64,1),256>>>(p_xrot, w_in, b_in, p_qkv,
        ROWS, 3*E_, E_, E_, E_, 3*E_, 0,0,0,0,0,0, 1, 1.f);
    // 7) S = Q K^T * 1/sqrt(hd)   (batched over B*H)
    sgemm_k<1,0><<<dim3(8,8,B_*H_),256>>>(p_qkv, p_qkv + E_, nullptr, p_P,
        T_, T_, HD_, 3*E_, 3*E_, T_,
        (long)T_*3*E_, (long)HD_, (long)T_*3*E_, (long)HD_,
        (long)H_*TT, TT, H_, 0.125f);
    // 8) softmax rows (in place) + attention column sums
    zero_k<<<(B_*T_+255)/256,256>>>(p_amsum, B_*T_);
    softmax_colsum_k<<<dim3(T_/16,H_,B_),256>>>(p_P, p_amsum);
    // 9) ctx = P @ V   (NN, batched)
    sgemm_k<0,0><<<dim3(1,8,B_*H_),256>>>(p_P, p_qkv + 2*E_, nullptr, p_ctx,
        T_, HD_, T_, T_, 3*E_, E_,
        (long)H_*TT, TT, (long)T_*3*E_, (long)HD_,
        (long)T_*E_, (long)HD_, H_, 1.f);
    // 10) attn_out = ctx @ w_out^T + b_out
    sgemm_k<1,0><<<dim3(8,64,1),256>>>(p_ctx, w_out, b_out, p_attnout,
        ROWS, E_, E_, E_, E_, E_, 0,0,0,0,0,0, 1, 1.f);
    // 11) divergence
    absdiff_k<<<(ROWS*E_+255)/256,256>>>(p_attnout, p_xrot, p_div, ROWS*E_);
    // 12) scorer hidden = ReLU(div @ ws1^T + bs1)  (reuse g_h2)
    sgemm_k<1,2><<<dim3(4,64,1),256>>>(p_div, ws1, bs1, p_h2,
        ROWS, E_/2, E_, E_, E_, E_/2, 0,0,0,0,0,0, 1, 1.f);
    // 13) base score
    base_k<<<ROWS/8,256>>>(p_h2, ws2, bs2, p_base);
    // 14) quaternion opposition chain
    qmean_k<<<ROWS,256>>>(p_xrot, p_qm);
    opp_k<<<ROWS/256,256>>>(p_qm, p_opp);
    wa_k<<<B_,256>>>(p_amsum, p_opp, p_wa);
    // 15) windowed anomalies
    anom_k<<<ROWS,256>>>(p_xrot, p_anom);
    // 16) combine -> intensity/strength/aq/pres
    combine_k<<<B_,1024>>>(p_opp, p_wa, p_anom, p_base, phase, p_aq, p_pres, p_inten);
    // 17) final phase rotation -> output
    final_k<<<ROWS,256>>>(p_xrot, p_aq, p_pres, p_inten, out);
}

// round 2
// speedup vs baseline: 2.0940x; 2.0940x over previous
#include <cuda_runtime.h>
#include <math.h>

#define B_   8
#define T_   1024
#define E_   1024
#define NB_  10
#define H_   16
#define HD_  64
#define ROWS (B_*T_)   // 8192

// ---------------- scratch (static device memory; no allocs) ----------------
__device__ float g_h1[ROWS*E_];          // 32 MB
__device__ float g_h2[ROWS*(E_/2)];      // 16 MB (reused for scorer hidden)
__device__ float g_scores[ROWS*NB_];
__device__ float g_xrot[ROWS*E_];        // 32 MB
__device__ float g_qkv[ROWS*3*E_];       // 96 MB
__device__ float g_P[134217728];         // 512 MB : B*H*T*T
__device__ float g_ctx[ROWS*E_];         // 32 MB
__device__ float g_attnout[ROWS*E_];     // 32 MB
__device__ float g_div[ROWS*E_];         // 32 MB
__device__ float g_base[ROWS];
__device__ float g_qm[ROWS*4];
__device__ float g_opp[ROWS];
__device__ float g_amsum[B_*T_];
__device__ float g_wa[B_];
__device__ float g_anom[ROWS];
__device__ float g_aq[ROWS*4];
__device__ float g_pres[ROWS];
__device__ float g_inten[ROWS];

// ---------------- helpers ----------------
__device__ __forceinline__ float geluf(float v){
    return 0.5f*v*(1.0f + erff(v*0.70710678118654752440f));
}
__device__ __forceinline__ float sigm(float v){ return 1.0f/(1.0f+expf(-v)); }

__device__ __forceinline__ float bred_sum(float v){
    __shared__ float sh[32];
    int lane = threadIdx.x & 31, w = threadIdx.x >> 5, nw = blockDim.x >> 5;
    #pragma unroll
    for (int o=16;o>0;o>>=1) v += __shfl_down_sync(0xffffffffu, v, o);
    if (lane==0) sh[w]=v;
    __syncthreads();
    if (w==0){
        v = (lane<nw)?sh[lane]:0.f;
        #pragma unroll
        for (int o=16;o>0;o>>=1) v += __shfl_down_sync(0xffffffffu, v, o);
        if (lane==0) sh[0]=v;
    }
    __syncthreads();
    float r = sh[0];
    __syncthreads();
    return r;
}

__device__ __forceinline__ float bred_max(float v){
    __shared__ float shm[32];
    int lane = threadIdx.x & 31, w = threadIdx.x >> 5, nw = blockDim.x >> 5;
    #pragma unroll
    for (int o=16;o>0;o>>=1) v = fmaxf(v, __shfl_down_sync(0xffffffffu, v, o));
    if (lane==0) shm[w]=v;
    __syncthreads();
    if (w==0){
        v = (lane<nw)?shm[lane]:-3.4e38f;
        #pragma unroll
        for (int o=16;o>0;o>>=1) v = fmaxf(v, __shfl_down_sync(0xffffffffu, v, o));
        if (lane==0) shm[0]=v;
    }
    __syncthreads();
    float r = shm[0];
    __syncthreads();
    return r;
}

__device__ __forceinline__ void qmulp(const float* q, const float* r, float* o){
    o[0]=q[0]*r[0]-q[1]*r[1]-q[2]*r[2]-q[3]*r[3];
    o[1]=q[0]*r[1]+q[1]*r[0]+q[2]*r[3]-q[3]*r[2];
    o[2]=q[0]*r[2]-q[1]*r[3]+q[2]*r[0]+q[3]*r[1];
    o[3]=q[0]*r[3]+q[1]*r[2]-q[2]*r[1]+q[3]*r[0];
}

__device__ __forceinline__ unsigned f2tf32(float f){
    unsigned u;
    asm("cvt.rna.tf32.f32 %0, %1;" : "=r"(u) : "f"(f));
    return u;
}

__device__ __forceinline__ void mma8(float* c, const unsigned* a, const unsigned* b){
    asm volatile("mma.sync.aligned.m16n8k8.row.col.f32.tf32.tf32.f32 "
        "{%0,%1,%2,%3}, {%4,%5,%6,%7}, {%8,%9}, {%0,%1,%2,%3};"
        : "+f"(c[0]),"+f"(c[1]),"+f"(c[2]),"+f"(c[3])
        : "r"(a[0]),"r"(a[1]),"r"(a[2]),"r"(a[3]), "r"(b[0]),"r"(b[1]));
}

// ---------------- tf32 tensor-core batched GEMM ----------------
// C = alpha * A @ op(B) + bias  with optional activation.
// TRB=1: op(B)=B^T (B is [N,K] row-major).  TRB=0: op(B)=B (B is [K,N]).
// ACT: 0 none, 1 GELU(exact), 2 ReLU
// Block tile 128x128xK16, 256 threads (8 warps, warp tile 64x32).
// Assumes M % 128 == 0 and K % 16 == 0 (true for all call sites). N guarded.
template<int TRB, int ACT>
__global__ void __launch_bounds__(256) tgemm_k(
    const float* __restrict__ Ag, const float* __restrict__ Bg,
    const float* __restrict__ bias, float* __restrict__ Cg,
    int M, int N, int K, int lda, int ldb, int ldc,
    long sAb, long sAh, long sBb, long sBh, long sCb, long sCh,
    int Hdiv, float alpha)
{
    int z  = blockIdx.z;
    int zb = z / Hdiv, zh = z - zb*Hdiv;
    const float* A = Ag + zb*sAb + zh*sAh;
    const float* B = Bg + zb*sBb + zh*sBh;
    float*       C = Cg + zb*sCb + zh*sCh;

    __shared__ unsigned As[16][132];
    __shared__ unsigned Bs[16][132];

    int tid  = threadIdx.x;
    int warp = tid >> 5, lane = tid & 31;
    int g = lane >> 2, t4 = lane & 3;
    int wm = warp & 1, wn = warp >> 1;          // 2 x 4 warp grid
    int row0 = blockIdx.y*128, col0 = blockIdx.x*128;

    float acc[4][4][4];
    #pragma unroll
    for (int i=0;i<4;i++)
        #pragma unroll
        for (int j=0;j<4;j++)
            #pragma unroll
            for (int k=0;k<4;k++) acc[i][j][k]=0.f;

    float4 ra[2], rb[2];

    // ---- gmem load of one K-slab into registers ----
    auto load_stage = [&](int k0){
        #pragma unroll
        for (int i=0;i<2;i++){
            int lid = tid + i*256;
            {   // A: [128 rows][16 cols], float4 per (row, quarter)
                int r = lid >> 2, q = lid & 3;
                ra[i] = *(const float4*)&A[(long)(row0+r)*lda + k0 + q*4];
            }
            if (TRB){ // B: [N,K] row-major, rows are output cols
                int r = lid >> 2, q = lid & 3;
                int gn = col0 + r;
                if (gn < N)
                    rb[i] = *(const float4*)&B[(long)gn*ldb + k0 + q*4];
                else
                    rb[i] = make_float4(0.f,0.f,0.f,0.f);
            } else {  // B: [K,N]
                int kk = lid >> 5, n4 = lid & 31;
                int gn = col0 + n4*4;
                if (gn < N)
                    rb[i] = *(const float4*)&B[(long)(k0+kk)*ldb + gn];
                else
                    rb[i] = make_float4(0.f,0.f,0.f,0.f);
            }
        }
    };

    auto store_stage = [&](){
        #pragma unroll
        for (int i=0;i<2;i++){
            int lid = tid + i*256;
            const float* pa = (const float*)&ra[i];
            const float* pb = (const float*)&rb[i];
            {
                int r = lid >> 2, q = lid & 3;
                #pragma unroll
                for (int j=0;j<4;j++) As[q*4+j][r] = f2tf32(pa[j]);
            }
            if (TRB){
                int r = lid >> 2, q = lid & 3;
                #pragma unroll
                for (int j=0;j<4;j++) Bs[q*4+j][r] = f2tf32(pb[j]);
            } else {
                int kk = lid >> 5, n4 = lid & 31;
                #pragma unroll
                for (int j=0;j<4;j++) Bs[kk][n4*4+j] = f2tf32(pb[j]);
            }
        }
    };

    load_stage(0);
    for (int k0=0; k0<K; k0+=16){
        store_stage();
        __syncthreads();
        bool more = (k0+16 < K);
        float4 na[2], nb[2];
        if (more){
            // stash current, load next into ra/rb via temp swap
            na[0]=ra[0]; na[1]=ra[1]; nb[0]=rb[0]; nb[1]=rb[1];
            load_stage(k0+16);
            // swap so ra/rb hold the NEXT tile after compute
            float4 t;
            t=ra[0]; ra[0]=na[0]; na[0]=t;
            t=ra[1]; ra[1]=na[1]; na[1]=t;
            t=rb[0]; rb[0]=nb[0]; nb[0]=t;
            t=rb[1]; rb[1]=nb[1]; nb[1]=t;
        }
        // compute from smem
        #pragma unroll
        for (int ks=0; ks<16; ks+=8){
            unsigned af[4][4], bf[4][2];
            #pragma unroll
            for (int im=0;im<4;im++){
                int m = wm*64 + im*16 + g;
                af[im][0]=As[ks+t4  ][m];
                af[im][1]=As[ks+t4  ][m+8];
                af[im][2]=As[ks+t4+4][m];
                af[im][3]=As[ks+t4+4][m+8];
            }
            #pragma unroll
            for (int jn=0;jn<4;jn++){
                int n = wn*32 + jn*8 + g;
                bf[jn][0]=Bs[ks+t4  ][n];
                bf[jn][1]=Bs[ks+t4+4][n];
            }
            #pragma unroll
            for (int im=0;im<4;im++)
                #pragma unroll
                for (int jn=0;jn<4;jn++)
                    mma8(acc[im][jn], af[im], bf[jn]);
        }
        __syncthreads();
        if (more){ ra[0]=na[0]; ra[1]=na[1]; rb[0]=nb[0]; rb[1]=nb[1]; }
    }

    // ---- epilogue ----
    #pragma unroll
    for (int im=0;im<4;im++){
        #pragma unroll
        for (int jn=0;jn<4;jn++){
            int gr = row0 + wm*64 + im*16 + g;
            int gc = col0 + wn*32 + jn*8 + t4*2;
            #pragma unroll
            for (int hh=0;hh<2;hh++){   // row, row+8
                int rr = gr + hh*8;
                if (rr >= M) continue;
                #pragma unroll
                for (int cc=0;cc<2;cc++){
                    int nn = gc + cc;
                    if (nn >= N) continue;
                    float v = acc[im][jn][hh*2+cc]*alpha;
                    if (bias) v += __ldg(&bias[nn]);
                    if (ACT==1)      v = geluf(v);
                    else if (ACT==2) v = fmaxf(v, 0.f);
                    C[(long)rr*ldc + nn] = v;
                }
            }
        }
    }
}

// ---------------- LayerNorm (biased var) + exact GELU, per row ----------------
__global__ void ln_gelu_k(const float* __restrict__ h, const float* __restrict__ g,
                          const float* __restrict__ bb, float* __restrict__ out)
{
    int row = blockIdx.x;
    const float* hr = h + (long)row*E_;
    float v[4]; float s=0.f, ss=0.f;
    #pragma unroll
    for (int i=0;i<4;i++){ v[i]=hr[threadIdx.x + i*256]; s+=v[i]; ss+=v[i]*v[i]; }
    s  = bred_sum(s);
    ss = bred_sum(ss);
    float mu   = s*(1.f/E_);
    float var  = ss*(1.f/E_) - mu*mu;
    float rstd = rsqrtf(var + 1e-5f);
    float* orow = out + (long)row*E_;
    #pragma unroll
    for (int i=0;i<4;i++){
        int c = threadIdx.x + i*256;
        float y = (v[i]-mu)*rstd*g[c] + bb[c];
        orow[c] = geluf(y);
    }
}

// ---------------- bias_scores = sigmoid(h2 @ w3^T + b3), N=10, K=512 --------
__global__ void bias_scores_k(const float* __restrict__ h2, const float* __restrict__ w3,
                              const float* __restrict__ b3, float* __restrict__ out)
{
    __shared__ float sw[NB_*512];
    for (int i=threadIdx.x;i<NB_*512;i+=256) sw[i]=w3[i];
    __syncthreads();
    int warp = threadIdx.x>>5, lane = threadIdx.x&31;
    long row = (long)blockIdx.x*8 + warp;
    const float* hr = h2 + row*512;
    float acc[NB_];
    #pragma unroll
    for (int j=0;j<NB_;j++) acc[j]=0.f;
    for (int k=lane;k<512;k+=32){
        float hv = hr[k];
        #pragma unroll
        for (int j=0;j<NB_;j++) acc[j] = fmaf(hv, sw[j*512+k], acc[j]);
    }
    #pragma unroll
    for (int j=0;j<NB_;j++){
        #pragma unroll
        for (int o=16;o>0;o>>=1) acc[j]+=__shfl_down_sync(0xffffffffu,acc[j],o);
    }
    if (lane==0){
        #pragma unroll
        for (int j=0;j<NB_;j++) out[row*NB_+j] = sigm(acc[j]+b3[j]);
    }
}

// ---------------- sequential quaternion bias correction ----------------
__global__ void bias_rotate_k(const float* __restrict__ x, const float* __restrict__ scores,
                              const float* __restrict__ quats, const float* __restrict__ thr,
                              float* __restrict__ out)
{
    int row = blockIdx.x;
    __shared__ float sq[NB_*4];
    __shared__ float ssc[NB_];
    if (threadIdx.x<NB_*4) sq[threadIdx.x]=quats[threadIdx.x];
    if (threadIdx.x<NB_)   ssc[threadIdx.x]=scores[(long)row*NB_+threadIdx.x];
    __syncthreads();
    float th = *thr;
    float4 vv = ((const float4*)x)[(long)row*256 + threadIdx.x];
    float r[4]={vv.x,vv.y,vv.z,vv.w};
    #pragma unroll
    for (int k=0;k<NB_;k++){
        if (ssc[k]>th){
            float o[4];
            qmulp(&sq[k*4], r, o);
            r[0]=o[0];r[1]=o[1];r[2]=o[2];r[3]=o[3];
        }
    }
    ((float4*)out)[(long)row*256+threadIdx.x] = make_float4(r[0],r[1],r[2],r[3]);
}

// ---------------- misc small kernels ----------------
__global__ void zero_k(float* p, int n){
    int i = blockIdx.x*blockDim.x + threadIdx.x;
    if (i<n) p[i]=0.f;
}

__global__ void absdiff_k(const float* __restrict__ a, const float* __restrict__ b,
                          float* __restrict__ o, int n){
    int i = blockIdx.x*blockDim.x + threadIdx.x;
    if (i<n) o[i]=fabsf(a[i]-b[i]);
}

// ---------------- softmax rows of P in-place + accumulate column sums -------
// grid: (T/16, H, B), block 256. Each thread owns 4 fixed columns.
__global__ void softmax_colsum_k(float* __restrict__ P, float* __restrict__ amsum)
{
    int b=blockIdx.z, h=blockIdx.y, q0=blockIdx.x*16;
    float* base = P + ((size_t)(b*H_+h)*T_ + q0)*(size_t)T_;
    float lacc[4]={0.f,0.f,0.f,0.f};
    for (int r=0;r<16;r++){
        float* rowp = base + (size_t)r*T_;
        float v[4]; float m=-3.4e38f;
        #pragma unroll
        for (int i=0;i<4;i++){ v[i]=rowp[threadIdx.x+i*256]; m=fmaxf(m,v[i]); }
        m = bred_max(m);
        float s=0.f;
        #pragma unroll
        for (int i=0;i<4;i++){ v[i]=expf(v[i]-m); s+=v[i]; }
        s = bred_sum(s);
        float inv = 1.f/s;
        #pragma unroll
        for (int i=0;i<4;i++){
            float p = v[i]*inv;
            rowp[threadIdx.x+i*256]=p;
            lacc[i]+=p;
        }
    }
    #pragma unroll
    for (int i=0;i<4;i++) atomicAdd(&amsum[b*T_ + threadIdx.x + i*256], lacc[i]);
}

// ---------------- base = sigmoid(ReLU-hidden @ ws2^T + bs2), N=1 ------------
__global__ void base_k(const float* __restrict__ hs, const float* __restrict__ ws2,
                       const float* __restrict__ bs2, float* __restrict__ out){
    int warp=threadIdx.x>>5, lane=threadIdx.x&31;
    long row=(long)blockIdx.x*8+warp;
    const float* hr = hs + row*512;
    float acc=0.f;
    for (int k=lane;k<512;k+=32) acc = fmaf(hr[k], ws2[k], acc);
    #pragma unroll
    for (int o=16;o>0;o>>=1) acc+=__shfl_down_sync(0xffffffffu,acc,o);
    if (lane==0) out[row]=sigm(acc+bs2[0]);
}

// ---------------- normalized-quaternion row means ----------------
__global__ void qmean_k(const float* __restrict__ x, float* __restrict__ qm){
    int row=blockIdx.x;
    float4 vv = ((const float4*)x)[(long)row*256+threadIdx.x];
    float n = sqrtf(vv.x*vv.x+vv.y*vv.y+vv.z*vv.z+vv.w*vv.w);
    float inv = 1.f/(n+1e-8f);
    float s0=bred_sum(vv.x*inv);
    float s1=bred_sum(vv.y*inv);
    float s2=bred_sum(vv.z*inv);
    float s3=bred_sum(vv.w*inv);
    if (threadIdx.x==0){
        qm[row*4+0]=s0*(1.f/256.f); qm[row*4+1]=s1*(1.f/256.f);
        qm[row*4+2]=s2*(1.f/256.f); qm[row*4+3]=s3*(1.f/256.f);
    }
}

__global__ void opp_k(const float* __restrict__ qm, float* __restrict__ opp){
    int idx = blockIdx.x*blockDim.x+threadIdx.x;
    if (idx>=ROWS) return;
    int t = idx & (T_-1);
    if (t==0){ opp[idx]=0.f; return; }
    float d = qm[idx*4+0]*qm[(idx-1)*4+0] + qm[idx*4+1]*qm[(idx-1)*4+1]
            + qm[idx*4+2]*qm[(idx-1)*4+2] + qm[idx*4+3]*qm[(idx-1)*4+3];
    opp[idx] = fminf(fmaxf(-d,0.f),1.f);
}

__global__ void wa_k(const float* __restrict__ amsum, const float* __restrict__ opp,
                     float* __restrict__ wa){
    int b=blockIdx.x;
    float s=0.f;
    const float scale = 1.f/((float)H_*(float)T_);
    for (int t=threadIdx.x;t<T_;t+=256)
        s += amsum[b*T_+t]*scale*opp[b*T_+t];
    s = bred_sum(s);
    if (threadIdx.x==0) wa[b]=s;
}

// ---------------- windowed (w=5) z-score anomalies ----------------
__global__ void anom_k(const float* __restrict__ x, float* __restrict__ out){
    int row=blockIdx.x; int b=row>>10; int t=row&1023;
    int st = t-2 > 0 ? t-2 : 0;
    int en = t+3 < T_ ? t+3 : T_;
    float n=(float)(en-st);
    float z=0.f;
    const float* xb = x + ((size_t)b*T_)*E_;
    for (int e=threadIdx.x;e<E_;e+=256){
        float s=0.f, ss=0.f;
        for (int w=st;w<en;w++){
            float v = xb[(size_t)w*E_+e];
            s+=v; ss+=v*v;
        }
        float mean=s/n;
        float var=(ss - s*s/n)/(n-1.f);
        float sd=sqrtf(fmaxf(var,0.f))+1e-8f;
        float xv=xb[(size_t)t*E_+e];
        z += fabsf(xv-mean)/sd;
    }
    z = bred_sum(z);
    if (threadIdx.x==0) out[row]=z*(1.f/E_);
}

// ---------------- combine scores + phase quaternion params (block per b) ----
__global__ void combine_k(const float* __restrict__ opp, const float* __restrict__ wa,
                          const float* __restrict__ anom, const float* __restrict__ base,
                          const float* __restrict__ phase,
                          float* __restrict__ aq, float* __restrict__ pres,
                          float* __restrict__ inten)
{
    int b=blockIdx.x, t=threadIdx.x;
    long idx=(long)b*T_+t;
    float o_n  = sigm(opp[idx]*2.f);
    float acv  = (t < T_-1) ? wa[b] : 0.f;
    float a_n  = sigm(acv*2.f);
    float an_n = sigm(anom[idx]-1.f);
    float so=bred_sum(o_n),   sso=bred_sum(o_n*o_n);
    float sa=bred_sum(a_n),   ssa=bred_sum(a_n*a_n);
    float sn=bred_sum(an_n),  ssn=bred_sum(an_n*an_n);
    const float N=(float)T_;
    float std_o = sqrtf(fmaxf((sso - so*so/N)/(N-1.f),0.f));
    float std_a = sqrtf(fmaxf((ssa - sa*sa/N)/(N-1.f),0.f));
    float std_n = sqrtf(fmaxf((ssn - sn*sn/N)/(N-1.f),0.f));
    float combined = (o_n*(std_o+0.1f)+a_n*(std_a+0.1f)+an_n*(std_n+0.1f))*(1.f/3.f);
    float cs = sigm((base[idx]+combined-0.5f)*2.f);          // /TEMP, TEMP=0.5
    float it = fminf(fmaxf((cs-0.3f)*(1.f/0.7f),0.f),1.f);
    float stg = 0.5f*it;                                     // PHASE_STRENGTH
    float a0 = phase[0]*stg, a1=phase[1]*stg, a2=phase[2]*stg;
    float chv=cosf(a0*0.5f), shv=sinf(a0*0.5f);
    aq[idx*4+0]=chv;
    aq[idx*4+1]=shv*cosf(a1);
    aq[idx*4+2]=shv*sinf(a1)*cosf(a2);
    aq[idx*4+3]=shv*sinf(a1)*sinf(a2);
    pres[idx]=1.f-stg*0.5f;
    inten[idx]=it;
}

// ---------------- final phase-filter rotation ----------------
__global__ void final_k(const float* __restrict__ x, const float* __restrict__ aq,
                        const float* __restrict__ pres, const float* __restrict__ inten,
                        float* __restrict__ out)
{
    int row=blockIdx.x;
    float4 vv=((const float4*)x)[(long)row*256+threadIdx.x];
    float r[4]={vv.x,vv.y,vv.z,vv.w};
    float it=inten[row];
    float res[4];
    if (it>0.1f){
        float q[4]={aq[row*4+0],aq[row*4+1],aq[row*4+2],aq[row*4+3]};
        float o[4]; qmulp(q,r,o);
        float p=pres[row];
        #pragma unroll
        for (int c=0;c<4;c++) res[c]=p*r[c]+(1.f-p)*o[c];
    } else {
        #pragma unroll
        for (int c=0;c<4;c++) res[c]=r[c];
    }
    ((float4*)out)[(long)row*256+threadIdx.x]=make_float4(res[0],res[1],res[2],res[3]);
}

// ---------------- host launcher ----------------
extern "C" void kernel_launch(void* const* d_in, const int* in_sizes, int n_in,
                              void* d_out, int out_size)
{
    const float* x          = (const float*)d_in[0];
    const float* w1         = (const float*)d_in[1];
    const float* b1         = (const float*)d_in[2];
    const float* ln_g       = (const float*)d_in[3];
    const float* ln_b       = (const float*)d_in[4];
    const float* w2         = (const float*)d_in[5];
    const float* b2         = (const float*)d_in[6];
    const float* w3         = (const float*)d_in[7];
    const float* b3         = (const float*)d_in[8];
    const float* bias_quats = (const float*)d_in[9];
    const float* bias_thr   = (const float*)d_in[10];
    const float* w_in       = (const float*)d_in[11];
    const float* b_in       = (const float*)d_in[12];
    const float* w_out      = (const float*)d_in[13];
    const float* b_out      = (const float*)d_in[14];
    const float* ws1        = (const float*)d_in[15];
    const float* bs1        = (const float*)d_in[16];
    const float* ws2        = (const float*)d_in[17];
    const float* bs2        = (const float*)d_in[18];
    const float* phase      = (const float*)d_in[19];
    float* out = (float*)d_out;

    float *p_h1,*p_h2,*p_scores,*p_xrot,*p_qkv,*p_P,*p_ctx,*p_attnout,*p_div,
          *p_base,*p_qm,*p_opp,*p_amsum,*p_wa,*p_anom,*p_aq,*p_pres,*p_inten;
    cudaGetSymbolAddress((void**)&p_h1,      g_h1);
    cudaGetSymbolAddress((void**)&p_h2,      g_h2);
    cudaGetSymbolAddress((void**)&p_scores,  g_scores);
    cudaGetSymbolAddress((void**)&p_xrot,    g_xrot);
    cudaGetSymbolAddress((void**)&p_qkv,     g_qkv);
    cudaGetSymbolAddress((void**)&p_P,       g_P);
    cudaGetSymbolAddress((void**)&p_ctx,     g_ctx);
    cudaGetSymbolAddress((void**)&p_attnout, g_attnout);
    cudaGetSymbolAddress((void**)&p_div,     g_div);
    cudaGetSymbolAddress((void**)&p_base,    g_base);
    cudaGetSymbolAddress((void**)&p_qm,      g_qm);
    cudaGetSymbolAddress((void**)&p_opp,     g_opp);
    cudaGetSymbolAddress((void**)&p_amsum,   g_amsum);
    cudaGetSymbolAddress((void**)&p_wa,      g_wa);
    cudaGetSymbolAddress((void**)&p_anom,    g_anom);
    cudaGetSymbolAddress((void**)&p_aq,      g_aq);
    cudaGetSymbolAddress((void**)&p_pres,    g_pres);
    cudaGetSymbolAddress((void**)&p_inten,   g_inten);

    const long TT = (long)T_*T_;

    // 1) h1 = x @ w1^T + b1
    tgemm_k<1,0><<<dim3(8,64,1),256>>>(x, w1, b1, p_h1,
        ROWS, E_, E_, E_, E_, E_, 0,0,0,0,0,0, 1, 1.f);
    // 2) LayerNorm + GELU (in place)
    ln_gelu_k<<<ROWS,256>>>(p_h1, ln_g, ln_b, p_h1);
    // 3) h2 = GELU(h1 @ w2^T + b2)
    tgemm_k<1,1><<<dim3(4,64,1),256>>>(p_h1, w2, b2, p_h2,
        ROWS, E_/2, E_, E_, E_, E_/2, 0,0,0,0,0,0, 1, 1.f);
    // 4) bias scores
    bias_scores_k<<<ROWS/8,256>>>(p_h2, w3, b3, p_scores);
    // 5) quaternion bias correction
    bias_rotate_k<<<ROWS,256>>>(x, p_scores, bias_quats, bias_thr, p_xrot);
    // 6) QKV projection
    tgemm_k<1,0><<<dim3(24,64,1),256>>>(p_xrot, w_in, b_in, p_qkv,
        ROWS, 3*E_, E_, E_, E_, 3*E_, 0,0,0,0,0,0, 1, 1.f);
    // 7) S = Q K^T * 1/sqrt(hd)   (batched over B*H)
    tgemm_k<1,0><<<dim3(8,8,B_*H_),256>>>(p_qkv, p_qkv + E_, nullptr, p_P,
        T_, T_, HD_, 3*E_, 3*E_, T_,
        (long)T_*3*E_, (long)HD_, (long)T_*3*E_, (long)HD_,
        (long)H_*TT, TT, H_, 0.125f);
    // 8) softmax rows (in place) + attention column sums
    zero_k<<<(B_*T_+255)/256,256>>>(p_amsum, B_*T_);
    softmax_colsum_k<<<dim3(T_/16,H_,B_),256>>>(p_P, p_amsum);
    // 9) ctx = P @ V   (NN, batched)
    tgemm_k<0,0><<<dim3(1,8,B_*H_),256>>>(p_P, p_qkv + 2*E_, nullptr, p_ctx,
        T_, HD_, T_, T_, 3*E_, E_,
        (long)H_*TT, TT, (long)T_*3*E_, (long)HD_,
        (long)T_*E_, (long)HD_, H_, 1.f);
    // 10) attn_out = ctx @ w_out^T + b_out
    tgemm_k<1,0><<<dim3(8,64,1),256>>>(p_ctx, w_out, b_out, p_attnout,
        ROWS, E_, E_, E_, E_, E_, 0,0,0,0,0,0, 1, 1.f);
    // 11) divergence
    absdiff_k<<<(ROWS*E_+255)/256,256>>>(p_attnout, p_xrot, p_div, ROWS*E_);
    // 12) scorer hidden = ReLU(div @ ws1^T + bs1)  (reuse g_h2)
    tgemm_k<1,2><<<dim3(4,64,1),256>>>(p_div, ws1, bs1, p_h2,
        ROWS, E_/2, E_, E_, E_, E_/2, 0,0,0,0,0,0, 1, 1.f);
    // 13) base score
    base_k<<<ROWS/8,256>>>(p_h2, ws2, bs2, p_base);
    // 14) quaternion opposition chain
    qmean_k<<<ROWS,256>>>(p_xrot, p_qm);
    opp_k<<<ROWS/256,256>>>(p_qm, p_opp);
    wa_k<<<B_,256>>>(p_amsum, p_opp, p_wa);
    // 15) windowed anomalies
    anom_k<<<ROWS,256>>>(p_xrot, p_anom);
    // 16) combine -> intensity/strength/aq/pres
    combine_k<<<B_,1024>>>(p_opp, p_wa, p_anom, p_base, phase, p_aq, p_pres, p_inten);
    // 17) final phase rotation -> output
    final_k<<<ROWS,256>>>(p_xrot, p_aq, p_pres, p_inten, out);
}

// round 3
// speedup vs baseline: 2.0940x; 1.0000x over previous
#include <cuda_runtime.h>
#include <math.h>

#define B_   8
#define T_   1024
#define E_   1024
#define NB_  10
#define H_   16
#define HD_  64
#define ROWS (B_*T_)   // 8192

// ---------------- scratch (static device memory; no allocs) ----------------
__device__ float g_h1[ROWS*E_];          // 32 MB
__device__ float g_h2[ROWS*(E_/2)];      // 16 MB (reused for scorer hidden)
__device__ float g_scores[ROWS*NB_];
__device__ float g_xrot[ROWS*E_];        // 32 MB
__device__ float g_qkv[ROWS*3*E_];       // 96 MB
__device__ float g_P[134217728];         // 512 MB : B*H*T*T
__device__ float g_ctx[ROWS*E_];         // 32 MB
__device__ float g_attnout[ROWS*E_];     // 32 MB
__device__ float g_div[ROWS*E_];         // 32 MB
__device__ float g_base[ROWS];
__device__ float g_qm[ROWS*4];
__device__ float g_opp[ROWS];
__device__ float g_amsum[B_*T_];
__device__ float g_wa[B_];
__device__ float g_anom[ROWS];
__device__ float g_aq[ROWS*4];
__device__ float g_pres[ROWS];
__device__ float g_inten[ROWS];

// ---------------- helpers ----------------
__device__ __forceinline__ float geluf(float v){
    return 0.5f*v*(1.0f + erff(v*0.70710678118654752440f));
}
__device__ __forceinline__ float sigm(float v){ return 1.0f/(1.0f+expf(-v)); }

__device__ __forceinline__ float bred_sum(float v){
    __shared__ float sh[32];
    int lane = threadIdx.x & 31, w = threadIdx.x >> 5, nw = blockDim.x >> 5;
    #pragma unroll
    for (int o=16;o>0;o>>=1) v += __shfl_down_sync(0xffffffffu, v, o);
    if (lane==0) sh[w]=v;
    __syncthreads();
    if (w==0){
        v = (lane<nw)?sh[lane]:0.f;
        #pragma unroll
        for (int o=16;o>0;o>>=1) v += __shfl_down_sync(0xffffffffu, v, o);
        if (lane==0) sh[0]=v;
    }
    __syncthreads();
    float r = sh[0];
    __syncthreads();
    return r;
}

__device__ __forceinline__ float bred_max(float v){
    __shared__ float shm[32];
    int lane = threadIdx.x & 31, w = threadIdx.x >> 5, nw = blockDim.x >> 5;
    #pragma unroll
    for (int o=16;o>0;o>>=1) v = fmaxf(v, __shfl_down_sync(0xffffffffu, v, o));
    if (lane==0) shm[w]=v;
    __syncthreads();
    if (w==0){
        v = (lane<nw)?shm[lane]:-3.4e38f;
        #pragma unroll
        for (int o=16;o>0;o>>=1) v = fmaxf(v, __shfl_down_sync(0xffffffffu, v, o));
        if (lane==0) shm[0]=v;
    }
    __syncthreads();
    float r = shm[0];
    __syncthreads();
    return r;
}

__device__ __forceinline__ void qmulp(const float* q, const float* r, float* o){
    o[0]=q[0]*r[0]-q[1]*r[1]-q[2]*r[2]-q[3]*r[3];
    o[1]=q[0]*r[1]+q[1]*r[0]+q[2]*r[3]-q[3]*r[2];
    o[2]=q[0]*r[2]-q[1]*r[3]+q[2]*r[0]+q[3]*r[1];
    o[3]=q[0]*r[3]+q[1]*r[2]-q[2]*r[1]+q[3]*r[0];
}

__device__ __forceinline__ unsigned f2tf32(float f){
    unsigned u;
    asm("cvt.rna.tf32.f32 %0, %1;" : "=r"(u) : "f"(f));
    return u;
}

__device__ __forceinline__ void mma8(float* c, const unsigned* a, const unsigned* b){
    asm volatile("mma.sync.aligned.m16n8k8.row.col.f32.tf32.tf32.f32 "
        "{%0,%1,%2,%3}, {%4,%5,%6,%7}, {%8,%9}, {%0,%1,%2,%3};"
        : "+f"(c[0]),"+f"(c[1]),"+f"(c[2]),"+f"(c[3])
        : "r"(a[0]),"r"(a[1]),"r"(a[2]),"r"(a[3]), "r"(b[0]),"r"(b[1]));
}

// ---------------- tf32 tensor-core batched GEMM ----------------
// C = alpha * A @ op(B) + bias  with optional activation.
// TRB=1: op(B)=B^T (B is [N,K] row-major).  TRB=0: op(B)=B (B is [K,N]).
// ACT: 0 none, 1 GELU(exact), 2 ReLU
// Block tile 128x128xK16, 256 threads (8 warps, warp tile 64x32).
// Assumes M % 128 == 0 and K % 16 == 0 (true for all call sites). N guarded.
template<int TRB, int ACT>
__global__ void __launch_bounds__(256) tgemm_k(
    const float* __restrict__ Ag, const float* __restrict__ Bg,
    const float* __restrict__ bias, float* __restrict__ Cg,
    int M, int N, int K, int lda, int ldb, int ldc,
    long sAb, long sAh, long sBb, long sBh, long sCb, long sCh,
    int Hdiv, float alpha)
{
    int z  = blockIdx.z;
    int zb = z / Hdiv, zh = z - zb*Hdiv;
    const float* A = Ag + zb*sAb + zh*sAh;
    const float* B = Bg + zb*sBb + zh*sBh;
    float*       C = Cg + zb*sCb + zh*sCh;

    __shared__ unsigned As[16][132];
    __shared__ unsigned Bs[16][132];

    int tid  = threadIdx.x;
    int warp = tid >> 5, lane = tid & 31;
    int g = lane >> 2, t4 = lane & 3;
    int wm = warp & 1, wn = warp >> 1;          // 2 x 4 warp grid
    int row0 = blockIdx.y*128, col0 = blockIdx.x*128;

    float acc[4][4][4];
    #pragma unroll
    for (int i=0;i<4;i++)
        #pragma unroll
        for (int j=0;j<4;j++)
            #pragma unroll
            for (int k=0;k<4;k++) acc[i][j][k]=0.f;

    float4 ra[2], rb[2];

    // ---- gmem load of one K-slab into registers ----
    auto load_stage = [&](int k0){
        #pragma unroll
        for (int i=0;i<2;i++){
            int lid = tid + i*256;
            {   // A: [128 rows][16 cols], float4 per (row, quarter)
                int r = lid >> 2, q = lid & 3;
                ra[i] = *(const float4*)&A[(long)(row0+r)*lda + k0 + q*4];
            }
            if (TRB){ // B: [N,K] row-major, rows are output cols
                int r = lid >> 2, q = lid & 3;
                int gn = col0 + r;
                if (gn < N)
                    rb[i] = *(const float4*)&B[(long)gn*ldb + k0 + q*4];
                else
                    rb[i] = make_float4(0.f,0.f,0.f,0.f);
            } else {  // B: [K,N]
                int kk = lid >> 5, n4 = lid & 31;
                int gn = col0 + n4*4;
                if (gn < N)
                    rb[i] = *(const float4*)&B[(long)(k0+kk)*ldb + gn];
                else
                    rb[i] = make_float4(0.f,0.f,0.f,0.f);
            }
        }
    };

    auto store_stage = [&](){
        #pragma unroll
        for (int i=0;i<2;i++){
            int lid = tid + i*256;
            const float* pa = (const float*)&ra[i];
            const float* pb = (const float*)&rb[i];
            {
                int r = lid >> 2, q = lid & 3;
                #pragma unroll
                for (int j=0;j<4;j++) As[q*4+j][r] = f2tf32(pa[j]);
            }
            if (TRB){
                int r = lid >> 2, q = lid & 3;
                #pragma unroll
                for (int j=0;j<4;j++) Bs[q*4+j][r] = f2tf32(pb[j]);
            } else {
                int kk = lid >> 5, n4 = lid & 31;
                #pragma unroll
                for (int j=0;j<4;j++) Bs[kk][n4*4+j] = f2tf32(pb[j]);
            }
        }
    };

    load_stage(0);
    for (int k0=0; k0<K; k0+=16){
        store_stage();
        __syncthreads();
        bool more = (k0+16 < K);
        float4 na[2], nb[2];
        if (more){
            // stash current, load next into ra/rb via temp swap
            na[0]=ra[0]; na[1]=ra[1]; nb[0]=rb[0]; nb[1]=rb[1];
            load_stage(k0+16);
            // swap so ra/rb hold the NEXT tile after compute
            float4 t;
            t=ra[0]; ra[0]=na[0]; na[0]=t;
            t=ra[1]; ra[1]=na[1]; na[1]=t;
            t=rb[0]; rb[0]=nb[0]; nb[0]=t;
            t=rb[1]; rb[1]=nb[1]; nb[1]=t;
        }
        // compute from smem
        #pragma unroll
        for (int ks=0; ks<16; ks+=8){
            unsigned af[4][4], bf[4][2];
            #pragma unroll
            for (int im=0;im<4;im++){
                int m = wm*64 + im*16 + g;
                af[im][0]=As[ks+t4  ][m];
                af[im][1]=As[ks+t4  ][m+8];
                af[im][2]=As[ks+t4+4][m];
                af[im][3]=As[ks+t4+4][m+8];
            }
            #pragma unroll
            for (int jn=0;jn<4;jn++){
                int n = wn*32 + jn*8 + g;
                bf[jn][0]=Bs[ks+t4  ][n];
                bf[jn][1]=Bs[ks+t4+4][n];
            }
            #pragma unroll
            for (int im=0;im<4;im++)
                #pragma unroll
                for (int jn=0;jn<4;jn++)
                    mma8(acc[im][jn], af[im], bf[jn]);
        }
        __syncthreads();
        if (more){ ra[0]=na[0]; ra[1]=na[1]; rb[0]=nb[0]; rb[1]=nb[1]; }
    }

    // ---- epilogue ----
    #pragma unroll
    for (int im=0;im<4;im++){
        #pragma unroll
        for (int jn=0;jn<4;jn++){
            int gr = row0 + wm*64 + im*16 + g;
            int gc = col0 + wn*32 + jn*8 + t4*2;
            #pragma unroll
            for (int hh=0;hh<2;hh++){   // row, row+8
                int rr = gr + hh*8;
                if (rr >= M) continue;
                #pragma unroll
                for (int cc=0;cc<2;cc++){
                    int nn = gc + cc;
                    if (nn >= N) continue;
                    float v = acc[im][jn][hh*2+cc]*alpha;
                    if (bias) v += __ldg(&bias[nn]);
                    if (ACT==1)      v = geluf(v);
                    else if (ACT==2) v = fmaxf(v, 0.f);
                    C[(long)rr*ldc + nn] = v;
                }
            }
        }
    }
}

// ---------------- LayerNorm (biased var) + exact GELU, per row ----------------
__global__ void ln_gelu_k(const float* __restrict__ h, const float* __restrict__ g,
                          const float* __restrict__ bb, float* __restrict__ out)
{
    int row = blockIdx.x;
    const float* hr = h + (long)row*E_;
    float v[4]; float s=0.f, ss=0.f;
    #pragma unroll
    for (int i=0;i<4;i++){ v[i]=hr[threadIdx.x + i*256]; s+=v[i]; ss+=v[i]*v[i]; }
    s  = bred_sum(s);
    ss = bred_sum(ss);
    float mu   = s*(1.f/E_);
    float var  = ss*(1.f/E_) - mu*mu;
    float rstd = rsqrtf(var + 1e-5f);
    float* orow = out + (long)row*E_;
    #pragma unroll
    for (int i=0;i<4;i++){
        int c = threadIdx.x + i*256;
        float y = (v[i]-mu)*rstd*g[c] + bb[c];
        orow[c] = geluf(y);
    }
}

// ---------------- bias_scores = sigmoid(h2 @ w3^T + b3), N=10, K=512 --------
__global__ void bias_scores_k(const float* __restrict__ h2, const float* __restrict__ w3,
                              const float* __restrict__ b3, float* __restrict__ out)
{
    __shared__ float sw[NB_*512];
    for (int i=threadIdx.x;i<NB_*512;i+=256) sw[i]=w3[i];
    __syncthreads();
    int warp = threadIdx.x>>5, lane = threadIdx.x&31;
    long row = (long)blockIdx.x*8 + warp;
    const float* hr = h2 + row*512;
    float acc[NB_];
    #pragma unroll
    for (int j=0;j<NB_;j++) acc[j]=0.f;
    for (int k=lane;k<512;k+=32){
        float hv = hr[k];
        #pragma unroll
        for (int j=0;j<NB_;j++) acc[j] = fmaf(hv, sw[j*512+k], acc[j]);
    }
    #pragma unroll
    for (int j=0;j<NB_;j++){
        #pragma unroll
        for (int o=16;o>0;o>>=1) acc[j]+=__shfl_down_sync(0xffffffffu,acc[j],o);
    }
    if (lane==0){
        #pragma unroll
        for (int j=0;j<NB_;j++) out[row*NB_+j] = sigm(acc[j]+b3[j]);
    }
}

// ---------------- sequential quaternion bias correction ----------------
__global__ void bias_rotate_k(const float* __restrict__ x, const float* __restrict__ scores,
                              const float* __restrict__ quats, const float* __restrict__ thr,
                              float* __restrict__ out)
{
    int row = blockIdx.x;
    __shared__ float sq[NB_*4];
    __shared__ float ssc[NB_];
    if (threadIdx.x<NB_*4) sq[threadIdx.x]=quats[threadIdx.x];
    if (threadIdx.x<NB_)   ssc[threadIdx.x]=scores[(long)row*NB_+threadIdx.x];
    __syncthreads();
    float th = *thr;
    float4 vv = ((const float4*)x)[(long)row*256 + threadIdx.x];
    float r[4]={vv.x,vv.y,vv.z,vv.w};
    #pragma unroll
    for (int k=0;k<NB_;k++){
        if (ssc[k]>th){
            float o[4];
            qmulp(&sq[k*4], r, o);
            r[0]=o[0];r[1]=o[1];r[2]=o[2];r[3]=o[3];
        }
    }
    ((float4*)out)[(long)row*256+threadIdx.x] = make_float4(r[0],r[1],r[2],r[3]);
}

// ---------------- misc small kernels ----------------
__global__ void zero_k(float* p, int n){
    int i = blockIdx.x*blockDim.x + threadIdx.x;
    if (i<n) p[i]=0.f;
}

__global__ void absdiff_k(const float* __restrict__ a, const float* __restrict__ b,
                          float* __restrict__ o, int n){
    int i = blockIdx.x*blockDim.x + threadIdx.x;
    if (i<n) o[i]=fabsf(a[i]-b[i]);
}

// ---------------- softmax rows of P in-place + accumulate column sums -------
// grid: (T/16, H, B), block 256. Each thread owns 4 fixed columns.
__global__ void softmax_colsum_k(float* __restrict__ P, float* __restrict__ amsum)
{
    int b=blockIdx.z, h=blockIdx.y, q0=blockIdx.x*16;
    float* base = P + ((size_t)(b*H_+h)*T_ + q0)*(size_t)T_;
    float lacc[4]={0.f,0.f,0.f,0.f};
    for (int r=0;r<16;r++){
        float* rowp = base + (size_t)r*T_;
        float v[4]; float m=-3.4e38f;
        #pragma unroll
        for (int i=0;i<4;i++){ v[i]=rowp[threadIdx.x+i*256]; m=fmaxf(m,v[i]); }
        m = bred_max(m);
        float s=0.f;
        #pragma unroll
        for (int i=0;i<4;i++){ v[i]=expf(v[i]-m); s+=v[i]; }
        s = bred_sum(s);
        float inv = 1.f/s;
        #pragma unroll
        for (int i=0;i<4;i++){
            float p = v[i]*inv;
            rowp[threadIdx.x+i*256]=p;
            lacc[i]+=p;
        }
    }
    #pragma unroll
    for (int i=0;i<4;i++) atomicAdd(&amsum[b*T_ + threadIdx.x + i*256], lacc[i]);
}

// ---------------- base = sigmoid(ReLU-hidden @ ws2^T + bs2), N=1 ------------
__global__ void base_k(const float* __restrict__ hs, const float* __restrict__ ws2,
                       const float* __restrict__ bs2, float* __restrict__ out){
    int warp=threadIdx.x>>5, lane=threadIdx.x&31;
    long row=(long)blockIdx.x*8+warp;
    const float* hr = hs + row*512;
    float acc=0.f;
    for (int k=lane;k<512;k+=32) acc = fmaf(hr[k], ws2[k], acc);
    #pragma unroll
    for (int o=16;o>0;o>>=1) acc+=__shfl_down_sync(0xffffffffu,acc,o);
    if (lane==0) out[row]=sigm(acc+bs2[0]);
}

// ---------------- normalized-quaternion row means ----------------
__global__ void qmean_k(const float* __restrict__ x, float* __restrict__ qm){
    int row=blockIdx.x;
    float4 vv = ((const float4*)x)[(long)row*256+threadIdx.x];
    float n = sqrtf(vv.x*vv.x+vv.y*vv.y+vv.z*vv.z+vv.w*vv.w);
    float inv = 1.f/(n+1e-8f);
    float s0=bred_sum(vv.x*inv);
    float s1=bred_sum(vv.y*inv);
    float s2=bred_sum(vv.z*inv);
    float s3=bred_sum(vv.w*inv);
    if (threadIdx.x==0){
        qm[row*4+0]=s0*(1.f/256.f); qm[row*4+1]=s1*(1.f/256.f);
        qm[row*4+2]=s2*(1.f/256.f); qm[row*4+3]=s3*(1.f/256.f);
    }
}

__global__ void opp_k(const float* __restrict__ qm, float* __restrict__ opp){
    int idx = blockIdx.x*blockDim.x+threadIdx.x;
    if (idx>=ROWS) return;
    int t = idx & (T_-1);
    if (t==0){ opp[idx]=0.f; return; }
    float d = qm[idx*4+0]*qm[(idx-1)*4+0] + qm[idx*4+1]*qm[(idx-1)*4+1]
            + qm[idx*4+2]*qm[(idx-1)*4+2] + qm[idx*4+3]*qm[(idx-1)*4+3];
    opp[idx] = fminf(fmaxf(-d,0.f),1.f);
}

__global__ void wa_k(const float* __restrict__ amsum, const float* __restrict__ opp,
                     float* __restrict__ wa){
    int b=blockIdx.x;
    float s=0.f;
    const float scale = 1.f/((float)H_*(float)T_);
    for (int t=threadIdx.x;t<T_;t+=256)
        s += amsum[b*T_+t]*scale*opp[b*T_+t];
    s = bred_sum(s);
    if (threadIdx.x==0) wa[b]=s;
}

// ---------------- windowed (w=5) z-score anomalies ----------------
__global__ void anom_k(const float* __restrict__ x, float* __restrict__ out){
    int row=blockIdx.x; int b=row>>10; int t=row&1023;
    int st = t-2 > 0 ? t-2 : 0;
    int en = t+3 < T_ ? t+3 : T_;
    float n=(float)(en-st);
    float z=0.f;
    const float* xb = x + ((size_t)b*T_)*E_;
    for (int e=threadIdx.x;e<E_;e+=256){
        float s=0.f, ss=0.f;
        for (int w=st;w<en;w++){
            float v = xb[(size_t)w*E_+e];
            s+=v; ss+=v*v;
        }
        float mean=s/n;
        float var=(ss - s*s/n)/(n-1.f);
        float sd=sqrtf(fmaxf(var,0.f))+1e-8f;
        float xv=xb[(size_t)t*E_+e];
        z += fabsf(xv-mean)/sd;
    }
    z = bred_sum(z);
    if (threadIdx.x==0) out[row]=z*(1.f/E_);
}

// ---------------- combine scores + phase quaternion params (block per b) ----
__global__ void combine_k(const float* __restrict__ opp, const float* __restrict__ wa,
                          const float* __restrict__ anom, const float* __restrict__ base,
                          const float* __restrict__ phase,
                          float* __restrict__ aq, float* __restrict__ pres,
                          float* __restrict__ inten)
{
    int b=blockIdx.x, t=threadIdx.x;
    long idx=(long)b*T_+t;
    float o_n  = sigm(opp[idx]*2.f);
    float acv  = (t < T_-1) ? wa[b] : 0.f;
    float a_n  = sigm(acv*2.f);
    float an_n = sigm(anom[idx]-1.f);
    float so=bred_sum(o_n),   sso=bred_sum(o_n*o_n);
    float sa=bred_sum(a_n),   ssa=bred_sum(a_n*a_n);
    float sn=bred_sum(an_n),  ssn=bred_sum(an_n*an_n);
    const float N=(float)T_;
    float std_o = sqrtf(fmaxf((sso - so*so/N)/(N-1.f),0.f));
    float std_a = sqrtf(fmaxf((ssa - sa*sa/N)/(N-1.f),0.f));
    float std_n = sqrtf(fmaxf((ssn - sn*sn/N)/(N-1.f),0.f));
    float combined = (o_n*(std_o+0.1f)+a_n*(std_a+0.1f)+an_n*(std_n+0.1f))*(1.f/3.f);
    float cs = sigm((base[idx]+combined-0.5f)*2.f);          // /TEMP, TEMP=0.5
    float it = fminf(fmaxf((cs-0.3f)*(1.f/0.7f),0.f),1.f);
    float stg = 0.5f*it;                                     // PHASE_STRENGTH
    float a0 = phase[0]*stg, a1=phase[1]*stg, a2=phase[2]*stg;
    float chv=cosf(a0*0.5f), shv=sinf(a0*0.5f);
    aq[idx*4+0]=chv;
    aq[idx*4+1]=shv*cosf(a1);
    aq[idx*4+2]=shv*sinf(a1)*cosf(a2);
    aq[idx*4+3]=shv*sinf(a1)*sinf(a2);
    pres[idx]=1.f-stg*0.5f;
    inten[idx]=it;
}

// ---------------- final phase-filter rotation ----------------
__global__ void final_k(const float* __restrict__ x, const float* __restrict__ aq,
                        const float* __restrict__ pres, const float* __restrict__ inten,
                        float* __restrict__ out)
{
    int row=blockIdx.x;
    float4 vv=((const float4*)x)[(long)row*256+threadIdx.x];
    float r[4]={vv.x,vv.y,vv.z,vv.w};
    float it=inten[row];
    float res[4];
    if (it>0.1f){
        float q[4]={aq[row*4+0],aq[row*4+1],aq[row*4+2],aq[row*4+3]};
        float o[4]; qmulp(q,r,o);
        float p=pres[row];
        #pragma unroll
        for (int c=0;c<4;c++) res[c]=p*r[c]+(1.f-p)*o[c];
    } else {
        #pragma unroll
        for (int c=0;c<4;c++) res[c]=r[c];
    }
    ((float4*)out)[(long)row*256+threadIdx.x]=make_float4(res[0],res[1],res[2],res[3]);
}

// ---------------- host launcher ----------------
extern "C" void kernel_launch(void* const* d_in, const int* in_sizes, int n_in,
                              void* d_out, int out_size)
{
    const float* x          = (const float*)d_in[0];
    const float* w1         = (const float*)d_in[1];
    const float* b1         = (const float*)d_in[2];
    const float* ln_g       = (const float*)d_in[3];
    const float* ln_b       = (const float*)d_in[4];
    const float* w2         = (const float*)d_in[5];
    const float* b2         = (const float*)d_in[6];
    const float* w3         = (const float*)d_in[7];
    const float* b3         = (const float*)d_in[8];
    const float* bias_quats = (const float*)d_in[9];
    const float* bias_thr   = (const float*)d_in[10];
    const float* w_in       = (const float*)d_in[11];
    const float* b_in       = (const float*)d_in[12];
    const float* w_out      = (const float*)d_in[13];
    const float* b_out      = (const float*)d_in[14];
    const float* ws1        = (const float*)d_in[15];
    const float* bs1        = (const float*)d_in[16];
    const float* ws2        = (const float*)d_in[17];
    const float* bs2        = (const float*)d_in[18];
    const float* phase      = (const float*)d_in[19];
    float* out = (float*)d_out;

    float *p_h1,*p_h2,*p_scores,*p_xrot,*p_qkv,*p_P,*p_ctx,*p_attnout,*p_div,
          *p_base,*p_qm,*p_opp,*p_amsum,*p_wa,*p_anom,*p_aq,*p_pres,*p_inten;
    cudaGetSymbolAddress((void**)&p_h1,      g_h1);
    cudaGetSymbolAddress((void**)&p_h2,      g_h2);
    cudaGetSymbolAddress((void**)&p_scores,  g_scores);
    cudaGetSymbolAddress((void**)&p_xrot,    g_xrot);
    cudaGetSymbolAddress((void**)&p_qkv,     g_qkv);
    cudaGetSymbolAddress((void**)&p_P,       g_P);
    cudaGetSymbolAddress((void**)&p_ctx,     g_ctx);
    cudaGetSymbolAddress((void**)&p_attnout, g_attnout);
    cudaGetSymbolAddress((void**)&p_div,     g_div);
    cudaGetSymbolAddress((void**)&p_base,    g_base);
    cudaGetSymbolAddress((void**)&p_qm,      g_qm);
    cudaGetSymbolAddress((void**)&p_opp,     g_opp);
    cudaGetSymbolAddress((void**)&p_amsum,   g_amsum);
    cudaGetSymbolAddress((void**)&p_wa,      g_wa);
    cudaGetSymbolAddress((void**)&p_anom,    g_anom);
    cudaGetSymbolAddress((void**)&p_aq,      g_aq);
    cudaGetSymbolAddress((void**)&p_pres,    g_pres);
    cudaGetSymbolAddress((void**)&p_inten,   g_inten);

    const long TT = (long)T_*T_;

    // 1) h1 = x @ w1^T + b1
    tgemm_k<1,0><<<dim3(8,64,1),256>>>(x, w1, b1, p_h1,
        ROWS, E_, E_, E_, E_, E_, 0,0,0,0,0,0, 1, 1.f);
    // 2) LayerNorm + GELU (in place)
    ln_gelu_k<<<ROWS,256>>>(p_h1, ln_g, ln_b, p_h1);
    // 3) h2 = GELU(h1 @ w2^T + b2)
    tgemm_k<1,1><<<dim3(4,64,1),256>>>(p_h1, w2, b2, p_h2,
        ROWS, E_/2, E_, E_, E_, E_/2, 0,0,0,0,0,0, 1, 1.f);
    // 4) bias scores
    bias_scores_k<<<ROWS/8,256>>>(p_h2, w3, b3, p_scores);
    // 5) quaternion bias correction
    bias_rotate_k<<<ROWS,256>>>(x, p_scores, bias_quats, bias_thr, p_xrot);
    // 6) QKV projection
    tgemm_k<1,0><<<dim3(24,64,1),256>>>(p_xrot, w_in, b_in, p_qkv,
        ROWS, 3*E_, E_, E_, E_, 3*E_, 0,0,0,0,0,0, 1, 1.f);
    // 7) S = Q K^T * 1/sqrt(hd)   (batched over B*H)
    tgemm_k<1,0><<<dim3(8,8,B_*H_),256>>>(p_qkv, p_qkv + E_, nullptr, p_P,
        T_, T_, HD_, 3*E_, 3*E_, T_,
        (long)T_*3*E_, (long)HD_, (long)T_*3*E_, (long)HD_,
        (long)H_*TT, TT, H_, 0.125f);
    // 8) softmax rows (in place) + attention column sums
    zero_k<<<(B_*T_+255)/256,256>>>(p_amsum, B_*T_);
    softmax_colsum_k<<<dim3(T_/16,H_,B_),256>>>(p_P, p_amsum);
    // 9) ctx = P @ V   (NN, batched)
    tgemm_k<0,0><<<dim3(1,8,B_*H_),256>>>(p_P, p_qkv + 2*E_, nullptr, p_ctx,
        T_, HD_, T_, T_, 3*E_, E_,
        (long)H_*TT, TT, (long)T_*3*E_, (long)HD_,
        (long)T_*E_, (long)HD_, H_, 1.f);
    // 10) attn_out = ctx @ w_out^T + b_out
    tgemm_k<1,0><<<dim3(8,64,1),256>>>(p_ctx, w_out, b_out, p_attnout,
        ROWS, E_, E_, E_, E_, E_, 0,0,0,0,0,0, 1, 1.f);
    // 11) divergence
    absdiff_k<<<(ROWS*E_+255)/256,256>>>(p_attnout, p_xrot, p_div, ROWS*E_);
    // 12) scorer hidden = ReLU(div @ ws1^T + bs1)  (reuse g_h2)
    tgemm_k<1,2><<<dim3(4,64,1),256>>>(p_div, ws1, bs1, p_h2,
        ROWS, E_/2, E_, E_, E_, E_/2, 0,0,0,0,0,0, 1, 1.f);
    // 13) base score
    base_k<<<ROWS/8,256>>>(p_h2, ws2, bs2, p_base);
    // 14) quaternion opposition chain
    qmean_k<<<ROWS,256>>>(p_xrot, p_qm);
    opp_k<<<ROWS/256,256>>>(p_qm, p_opp);
    wa_k<<<B_,256>>>(p_amsum, p_opp, p_wa);
    // 15) windowed anomalies
    anom_k<<<ROWS,256>>>(p_xrot, p_anom);
    // 16) combine -> intensity/strength/aq/pres
    combine_k<<<B_,1024>>>(p_opp, p_wa, p_anom, p_base, phase, p_aq, p_pres, p_inten);
    // 17) final phase rotation -> output
    final_k<<<ROWS,256>>>(p_xrot, p_aq, p_pres, p_inten, out);
}